// round 1
// baseline (speedup 1.0000x reference)
#include <cuda_runtime.h>

#define B_   4096
#define F_   100
#define D_   64
#define TPB  128
#define NPAIR 4950

typedef unsigned long long ull;

// Packed fp32x2 math (Blackwell sm_10x; 2x fp32 FMA throughput vs 3-reg FFMA)
static __device__ __forceinline__ ull fma2(ull a, ull b, ull c) {
    ull d; asm("fma.rn.f32x2 %0, %1, %2, %3;" : "=l"(d) : "l"(a), "l"(b), "l"(c)); return d;
}
static __device__ __forceinline__ ull mul2(ull a, ull b) {
    ull d; asm("mul.rn.f32x2 %0, %1, %2;" : "=l"(d) : "l"(a), "l"(b)); return d;
}
static __device__ __forceinline__ float2 u2f(ull r) {
    float2 v; asm("mov.b64 {%0,%1}, %2;" : "=f"(v.x), "=f"(v.y) : "l"(r)); return v;
}

// Shared memory layout (floats):
//   Xs  [100][68]  padded X tile            0     .. 6800
//   Wt  [32][64]   slots 0-15: wq cols*0.25, 16-31: wk cols   6800 .. 8848
//   wvc [64]       wv column 0              8848  .. 8912
//   Qs  [100][16]                           8912  .. 10512
//   Kv  [100][18]  k0..k15, vcol, pad       10512 .. 12312
//   z0s [100]                               12312 .. 12412
//   xc0 [100]                               12412 .. 12512
#define SMEM_FLOATS 12512

__global__ void __launch_bounds__(TPB) dcap_kernel(
    const float* __restrict__ x,  const float* __restrict__ wq,
    const float* __restrict__ wk, const float* __restrict__ wv,
    float* __restrict__ out)
{
    extern __shared__ float sm[];
    float* Xs  = sm;
    float* Wt  = sm + 6800;
    float* wvc = sm + 8848;
    float* Qs  = sm + 8912;
    float* Kv  = sm + 10512;
    float* z0s = sm + 12312;
    float* xc0 = sm + 12412;

    const int t = threadIdx.x;
    const int b = blockIdx.x;

    // ---- Load X tile (coalesced float4 -> padded smem rows of 68) ----
    const float4* gx = (const float4*)(x + (size_t)b * (F_ * D_));
    #pragma unroll
    for (int i = t; i < F_ * D_ / 4; i += TPB) {
        int f = i >> 4, c = i & 15;
        *(float4*)(Xs + f * 68 + c * 4) = gx[i];
    }
    // ---- Weights: Wt[slot][d]; slots 0..15 = wq col h (pre-scaled by 0.25), 16..31 = wk col h
    for (int i = t; i < 2048; i += TPB) {
        int s = i >> 6, d = i & 63;
        Wt[s * 64 + d] = (s < 16) ? wq[d * 64 + s] * 0.25f : wk[d * 64 + (s - 16)];
    }
    if (t < 64) wvc[t] = wv[t * 64];
    __syncthreads();

    if (t < F_) xc0[t] = Xs[t * 68];

    // ---- Q/K projection: 200 items = (50 row-pairs) x (4 groups of 8 slots) ----
    for (int it = t; it < 200; it += TPB) {
        int fp = it % 50, grp = it / 50;
        int f0 = fp * 2, s0 = grp * 8;
        const ull* xr0 = (const ull*)(Xs + f0 * 68);
        const ull* xr1 = (const ull*)(Xs + f0 * 68 + 68);
        const ull* wr  = (const ull*)(Wt + s0 * 64);
        ull a0[8], a1[8];
        #pragma unroll
        for (int k = 0; k < 8; k++) { a0[k] = 0ull; a1[k] = 0ull; }
        #pragma unroll 4
        for (int dd = 0; dd < 32; dd++) {
            ull xv0 = xr0[dd], xv1 = xr1[dd];
            #pragma unroll
            for (int k = 0; k < 8; k++) {
                ull w = wr[k * 32 + dd];   // broadcast across lanes sharing grp
                a0[k] = fma2(xv0, w, a0[k]);
                a1[k] = fma2(xv1, w, a1[k]);
            }
        }
        #pragma unroll
        for (int k = 0; k < 8; k++) {
            float2 v0 = u2f(a0[k]), v1 = u2f(a1[k]);
            float r0 = v0.x + v0.y, r1 = v1.x + v1.y;
            int slot = s0 + k;
            if (slot < 16) { Qs[f0 * 16 + slot] = r0; Qs[(f0 + 1) * 16 + slot] = r1; }
            else           { Kv[f0 * 18 + slot - 16] = r0; Kv[(f0 + 1) * 18 + slot - 16] = r1; }
        }
    }
    // ---- v column (head0/hid0 of x@wv) ----
    if (t < F_) {
        const ull* xr = (const ull*)(Xs + t * 68);
        const ull* wr = (const ull*)wvc;
        ull a0 = 0ull, a1 = 0ull;
        #pragma unroll
        for (int dd = 0; dd < 32; dd += 2) {
            a0 = fma2(xr[dd],     wr[dd],     a0);
            a1 = fma2(xr[dd + 1], wr[dd + 1], a1);
        }
        float2 v0 = u2f(a0), v1 = u2f(a1);
        Kv[t * 18 + 16] = (v0.x + v1.x) + (v0.y + v1.y);
    }
    __syncthreads();

    // ---- Attention row per thread. Scores = q.k/4 are O(1..10): exp() cannot
    //      overflow fp32, so skip max-subtraction (mathematically identical softmax).
    if (t < F_) {
        const ull* qr = (const ull*)(Qs + t * 16);
        ull q0 = qr[0], q1 = qr[1], q2 = qr[2], q3 = qr[3];
        ull q4 = qr[4], q5 = qr[5], q6 = qr[6], q7 = qr[7];
        float denom = 0.f, zacc = 0.f;
        for (int g = 0; g < F_; g++) {
            const ull* kr = (const ull*)(Kv + g * 18);   // broadcast: all lanes same g
            ull e0 = mul2(q0, kr[0]);
            ull e1 = mul2(q1, kr[1]);
            e0 = fma2(q2, kr[2], e0);
            e1 = fma2(q3, kr[3], e1);
            e0 = fma2(q4, kr[4], e0);
            e1 = fma2(q5, kr[5], e1);
            e0 = fma2(q6, kr[6], e0);
            e1 = fma2(q7, kr[7], e1);
            float2 ea = u2f(e0), eb = u2f(e1);
            float s  = (ea.x + eb.x) + (ea.y + eb.y);
            float vg = Kv[g * 18 + 16];
            float ex = __expf(s);
            denom += ex;
            zacc = fmaf(ex, vg, zacc);
        }
        z0s[t] = zacc / denom;
    }
    __syncthreads();

    // ---- Pairwise output: p[pair(i,j)] = z0[i] * x[j,0], coalesced per row ----
    float* ob = out + (size_t)b * NPAIR;
    int rowoff = 0;
    #pragma unroll 1
    for (int i = 0; i < F_ - 1; i++) {
        float zi = z0s[i];
        int cnt = F_ - 1 - i;
        if (t < cnt) ob[rowoff + t] = zi * xc0[i + 1 + t];
        rowoff += cnt;
    }
}

extern "C" void kernel_launch(void* const* d_in, const int* in_sizes, int n_in,
                              void* d_out, int out_size)
{
    const float* x  = (const float*)d_in[0];
    const float* wq = (const float*)d_in[1];
    const float* wk = (const float*)d_in[2];
    const float* wv = (const float*)d_in[3];
    float* out = (float*)d_out;
    (void)in_sizes; (void)n_in; (void)out_size;

    const int smem_bytes = SMEM_FLOATS * (int)sizeof(float);   // 50048 > 48KB default
    cudaFuncSetAttribute(dcap_kernel, cudaFuncAttributeMaxDynamicSharedMemorySize, smem_bytes);
    dcap_kernel<<<B_, TPB, smem_bytes>>>(x, wq, wk, wv, out);
}